// round 13
// baseline (speedup 1.0000x reference)
#include <cuda_runtime.h>
#include <cuda_fp16.h>
#include <math_constants.h>
#include <cstdint>

#define B_   16
#define CIN  256
#define COUT 256
#define H_   64
#define W_   64
#define NK   4

// ---------------------------------------------------------------------------
// Device scratch (allocation-free rule)
// ---------------------------------------------------------------------------
// A operand (fp16, m16n8k16 fragment order):
//   per (b,tap): [gk 16][mtile 16][lane 32][8 halves] = 65536 halves
//   (gk = 16-channel group = cchunk*2+kstep)
__device__ __align__(1024) __half g_WtFh[(size_t)B_ * 9 * 65536];          // 18.9 MB
// B operand (fp16 fragment order), 3 dx-shifted padded copies:
//   per (dx,b,h): [gk 16][w8 8][lane 32][2 u32] = 16384 halves
__device__ __align__(1024) __half g_xBFh[(size_t)3 * B_ * 66 * 16384];     // 103.8 MB

// ---------------------------------------------------------------------------
__device__ __forceinline__ uint32_t smem_u32(const void* p) {
    uint32_t a;
    asm("{ .reg .u64 t; cvta.to.shared.u64 t, %1; cvt.u32.u64 %0, t; }" : "=r"(a) : "l"(p));
    return a;
}
#define CP_ASYNC16(sm, g) \
    asm volatile("cp.async.cg.shared.global [%0], [%1], 16;" :: "r"(sm), "l"(g))
#define CP_COMMIT() asm volatile("cp.async.commit_group;" ::: "memory")
#define CP_WAIT1()  asm volatile("cp.async.wait_group 1;" ::: "memory")

__device__ __forceinline__ void mma_f16(float* d, const uint32_t* a, const uint32_t* b) {
    asm volatile(
        "mma.sync.aligned.m16n8k16.row.col.f32.f16.f16.f32 "
        "{%0,%1,%2,%3}, {%4,%5,%6,%7}, {%8,%9}, {%0,%1,%2,%3};"
        : "+f"(d[0]), "+f"(d[1]), "+f"(d[2]), "+f"(d[3])
        : "r"(a[0]), "r"(a[1]), "r"(a[2]), "r"(a[3]), "r"(b[0]), "r"(b[1]));
}

// ---------------------------------------------------------------------------
// Build one 9x9 interpolation matrix (scaled by lambda) into R[81].
// ---------------------------------------------------------------------------
__device__ void rot_build(float t, float s, float lam, float* R) {
    float x = cosf(t) * s;
    float y = sinf(t) * s;

    float M[81];
#pragma unroll
    for (int i = 0; i < 81; i++) M[i] = 0.f;

    bool pos = (t >= 0.f);
    bool big = (s >= 1.f);
    bool m1  = (fabsf(t) <= (float)(CUDART_PI / 4.0));

    if (pos) {
        float a = x - y, b = x * y, c = x + y, d = a * c, e = a + c;
        if (m1 && big) {
            M[0] = a;        M[1] = 1.f - a;
            M[9+1] = 1.f-y;  M[9+2] = y;
            M[18+2] = a;     M[18+5] = 1.f-a;
            M[27+0] = y;     M[27+3] = 1.f-y;
            M[45+5] = 1.f-y; M[45+8] = y;
            M[54+3] = 1.f-a; M[54+6] = a;
            M[63+6] = y;     M[63+7] = 1.f-y;
            M[72+7] = 1.f-a; M[72+8] = a;
        } else if (m1 && !big) {
            M[0] = d;  M[1] = a-d;  M[3] = c-d;  M[4] = 1.f-e+d;
            M[9+1] = x-b;  M[9+2] = b;  M[9+4] = 1.f-c+b;  M[9+5] = y-b;
            M[18+1] = c-d; M[18+2] = d; M[18+4] = 1.f-e+d; M[18+5] = a-d;
            M[27+0] = b;   M[27+1] = y-b; M[27+3] = x-b;   M[27+4] = 1.f-c+b;
            M[45+4] = 1.f-c+b; M[45+5] = x-b; M[45+7] = y-b; M[45+8] = b;
            M[54+3] = a-d; M[54+4] = 1.f-e+d; M[54+6] = d;  M[54+7] = c-d;
            M[63+3] = y-b; M[63+4] = 1.f-c+b; M[63+6] = b;  M[63+7] = x-b;
            M[72+4] = 1.f-e+d; M[72+5] = c-d; M[72+7] = a-d; M[72+8] = d;
        } else {
            M[0] = a;        M[1] = 1.f-a;
            M[9+1] = x-b;    M[9+2] = b;   M[9+4] = 1.f-c+b; M[9+5] = y-b;
            M[18+2] = a;     M[18+5] = 1.f-a;
            M[27+0] = b;     M[27+1] = y-b; M[27+3] = x-b;  M[27+4] = 1.f-c+b;
            M[45+4] = 1.f-c+b; M[45+5] = x-b; M[45+7] = y-b; M[45+8] = b;
            M[54+3] = 1.f-a; M[54+6] = a;
            M[63+3] = y-b;   M[63+4] = 1.f-c+b; M[63+6] = b; M[63+7] = x-b;
            M[72+7] = 1.f-a; M[72+8] = a;
        }
    } else {
        float yp = -y;
        float ap = x - yp, bp = x * yp, cp = x + yp, dp = ap * cp, ep = ap + cp;
        if (m1 && big) {
            M[0] = cp;        M[3] = 1.f-cp;
            M[9+0] = yp;      M[9+1] = 1.f-yp;
            M[18+1] = 1.f-cp; M[18+2] = cp;
            M[27+3] = 1.f-yp; M[27+6] = yp;
            M[45+2] = yp;     M[45+5] = 1.f-yp;
            M[54+6] = cp;     M[54+7] = 1.f-cp;
            M[63+7] = 1.f-yp; M[63+8] = yp;
            M[72+5] = 1.f-cp; M[72+8] = cp;
        } else if (m1 && !big) {
            M[0] = dp;  M[1] = cp-dp;  M[3] = ap-dp;  M[4] = 1.f-ep+dp;
            M[9+0] = bp;   M[9+1] = x-bp;  M[9+3] = yp-bp;   M[9+4] = 1.f-cp+bp;
            M[18+1] = ap-dp; M[18+2] = dp; M[18+4] = 1.f-ep+dp; M[18+5] = cp-dp;
            M[27+1] = yp-bp; M[27+2] = bp; M[27+4] = 1.f-cp+bp; M[27+5] = x-bp;
            M[45+3] = x-bp;  M[45+4] = 1.f-cp+bp; M[45+6] = bp; M[45+7] = yp-bp;
            M[54+3] = cp-dp; M[54+4] = 1.f-ep+dp; M[54+6] = dp; M[54+7] = ap-dp;
            M[63+4] = 1.f-cp+bp; M[63+5] = yp-bp; M[63+7] = x-bp; M[63+8] = bp;
            M[72+4] = 1.f-ep+dp; M[72+5] = ap-dp; M[72+7] = cp-dp; M[72+8] = dp;
        } else {
            M[0] = cp;        M[3] = 1.f-cp;
            M[9+0] = bp;      M[9+1] = x-bp; M[9+3] = yp-bp; M[9+4] = 1.f-cp+bp;
            M[18+1] = 1.f-cp; M[18+2] = cp;
            M[27+3] = x-bp;   M[27+4] = 1.f-cp+bp; M[27+6] = bp; M[27+7] = yp-bp;
            M[45+1] = yp-bp;  M[45+2] = bp; M[45+4] = 1.f-cp+bp; M[45+5] = x-bp;
            M[54+6] = cp;     M[54+7] = 1.f-cp;
            M[63+4] = 1.f-cp+bp; M[63+5] = yp-bp; M[63+7] = x-bp; M[63+8] = bp;
            M[72+5] = 1.f-cp; M[72+8] = cp;
        }
    }
    M[40] = 1.f;

#pragma unroll
    for (int i = 0; i < 81; i++) R[i] = M[i] * lam;
}

// ---------------------------------------------------------------------------
// Kernel 1 (fused rot + wtrans): transformed weights -> A fp16 fragment order.
// Grid (256 o, 16 b), 256 threads = c. Threads 0..3 build the rot matrices.
// ---------------------------------------------------------------------------
__global__ void wtrans_kernel(const float* __restrict__ weight,
                              const float* __restrict__ thetas,
                              const float* __restrict__ scales,
                              const float* __restrict__ lambdas) {
    __shared__ float rs[NK * 81];
    int b = blockIdx.y;
    int o = blockIdx.x;
    int c = threadIdx.x;
    if (c < NK) {
        int idx = b * NK + c;
        rot_build(thetas[idx], scales[idx], lambdas[idx], &rs[c * 81]);
    }
    __syncthreads();

    float acc[9];
#pragma unroll
    for (int i = 0; i < 9; i++) acc[i] = 0.f;

#pragma unroll
    for (int n = 0; n < NK; n++) {
        const float* wp = weight + (((size_t)n * COUT + o) * CIN + c) * 9;
        float wv[9];
#pragma unroll
        for (int j = 0; j < 9; j++) wv[j] = wp[j];
        const float* r = &rs[n * 81];
#pragma unroll
        for (int i = 0; i < 9; i++)
#pragma unroll
            for (int j = 0; j < 9; j++)
                acc[i] = fmaf(r[i * 9 + j], wv[j], acc[i]);
    }

    int gk     = c >> 4;              // 16-channel group
    int mtile  = o >> 4;
    int lane   = (o & 7) * 4 + ((c >> 1) & 3);
    int r      = ((o >> 3) & 1) | (((c >> 3) & 1) << 1);
    int t      = c & 1;
    size_t base = (size_t)(b * 9) * 65536
                + ((size_t)gk * 16 + mtile) * 256 + lane * 8 + r * 2 + t;
#pragma unroll
    for (int tap = 0; tap < 9; tap++)
        g_WtFh[base + (size_t)tap * 65536] = __float2half(acc[tap]);
}

// ---------------------------------------------------------------------------
// Kernel 2: x -> B fp16 fragment order, 3 dx copies from ONE smem staging pass.
// Block = (b,h): 1056 blocks, 256 threads.
// ---------------------------------------------------------------------------
__global__ void pad_kernel(const float* __restrict__ x) {
    __shared__ __half sx[256 * 66];       // [c][w], row stride 66 halves
    int id = blockIdx.x;                  // b*66 + h
    int h = id % 66;
    int b = id / 66;
    int hs = h - 1;
    bool hok = (hs >= 0 && hs < H_);
    int tid = threadIdx.x;

    if (hok) {
        int wl = tid & 63;
        int cs = tid >> 6;
        for (int c0 = 0; c0 < 256; c0 += 4) {
            int c = c0 + cs;
            float v = x[((size_t)(b * CIN + c) * H_ + hs) * W_ + wl];
            sx[c * 66 + wl] = __float2half(v);
        }
    }
    __syncthreads();

    for (int dx = 0; dx < 3; dx++) {
        uint32_t* dst = (uint32_t*)(g_xBFh + ((size_t)(dx * 16 + b) * 66 + h) * 16384);
        for (int u = tid; u < 8192; u += 256) {
            int reg  = u & 1;
            int lane = (u >> 1) & 31;
            int w8   = (u >> 6) & 7;
            int gk   = u >> 9;
            int c = gk * 16 + reg * 8 + (lane & 3) * 2;
            int w = w8 * 8 + (lane >> 2) - 1 + dx;
            uint32_t val = 0;
            if (hok && w >= 0 && w < W_) {
                __half2 hv;
                hv.x = sx[c * 66 + w];
                hv.y = sx[(c + 1) * 66 + w];
                val = *(uint32_t*)&hv;
            }
            dst[u] = val;
        }
    }
}

// ---------------------------------------------------------------------------
// Kernel 3: fp16 mma.sync (m16n8k16) GEMM conv.
// CTA: 128 o x 128 n (2 rows x 64 w), 128 threads, 4 warps (2m x 2n),
// warp tile 64 x 64. K = 36 chunks of 64 c (tap-major; 4 k16 steps each) —
// halved barrier count vs 32-c chunks. 3-stage cp.async, 32KB/stage ->
// 96KB smem, 2 CTAs/SM.
// Stage: A [ks 4][mtl 8][lane 32][16B] = 16KB,
//        B [ks 4][row 2][w8 8][lp 16][16B] = 16KB.
// ---------------------------------------------------------------------------
#define STAGE_U32 8192                  // uint32 per stage (32KB)
#define DYN_SMEM (3 * STAGE_U32 * 4)

__global__ void __launch_bounds__(128, 2)
conv_mma_kernel(float* __restrict__ out) {
    extern __shared__ uint32_t sm[];

    const int tid = threadIdx.x;
    const int wid = tid >> 5;
    const int lane = tid & 31;
    const int b  = blockIdx.z;
    const int my = blockIdx.y;          // m tile (0..1)
    const int h0 = blockIdx.x * 2;      // output rows h0..h0+1

    const int wm = wid >> 1;            // 0..1  (warp m: 64 rows)
    const int row = wid & 1;            // warp n: one full output row (64 w)

    const uint32_t smb = smem_u32(sm);

    float acc[4][8][4];
#pragma unroll
    for (int i = 0; i < 4; i++)
#pragma unroll
        for (int j = 0; j < 8; j++)
#pragma unroll
            for (int k = 0; k < 4; k++) acc[i][j][k] = 0.f;

    const __half* Abase = g_WtFh + (size_t)b * 9 * 65536;
    const __half* Bbase = g_xBFh;

    auto issue_stage = [&](int chunk, int slot) {
        int tap = chunk >> 2;                         // 0..8
        int g0  = (chunk & 3) * 4;                    // base gk (4 gk per chunk)
        int dy  = tap / 3, dx = tap - dy * 3;
        uint32_t sbase = smb + slot * (STAGE_U32 * 4);
        const __half* Ab = Abase + (size_t)tap * 65536;
        size_t bhbase = ((size_t)(dx * 16 + b) * 66 + (h0 + dy)) * 16384;
        // A: 1024 x 16B
#pragma unroll
        for (int r = 0; r < 8; r++) {
            int u = tid + r * 128;                    // 0..1023
            int ks  = u >> 8;
            int mtl = (u >> 5) & 7;
            int ln  = u & 31;
            const __half* g = Ab + ((size_t)((g0 + ks) * 16) + (my * 8 + mtl)) * 256 + ln * 8;
            CP_ASYNC16(sbase + u * 16, g);
        }
        // B: 1024 x 16B (two h rows)
#pragma unroll
        for (int r = 0; r < 8; r++) {
            int u = tid + r * 128;                    // 0..1023
            int ks = u >> 8;
            int rw = (u >> 7) & 1;
            int w8 = (u >> 4) & 7;
            int lp = u & 15;
            const __half* g = Bbase + bhbase + (size_t)rw * 16384
                              + (size_t)((g0 + ks) * 8 + w8) * 128 + lp * 8;
            CP_ASYNC16(sbase + 16384 + u * 16, g);
        }
    };

    issue_stage(0, 0); CP_COMMIT();
    issue_stage(1, 1); CP_COMMIT();

    for (int i = 0; i < 36; i++) {
        CP_WAIT1();
        __syncthreads();
        if (i + 2 < 36) issue_stage(i + 2, (i + 2) % 3);
        CP_COMMIT();

        const uint32_t* st = sm + (i % 3) * STAGE_U32;
#pragma unroll
        for (int ks = 0; ks < 4; ks++) {
            uint32_t af[4][4];
#pragma unroll
            for (int ii = 0; ii < 4; ii++) {
                const uint4 v = *(const uint4*)(st + ((ks * 8 + wm * 4 + ii) * 32 + lane) * 4);
                af[ii][0] = v.x; af[ii][1] = v.y; af[ii][2] = v.z; af[ii][3] = v.w;
            }
#pragma unroll
            for (int jj = 0; jj < 8; jj++) {
                uint32_t bf[2];
                const uint2 v = *(const uint2*)(st + 4096 +
                                 (((ks * 2 + row) * 8 + jj) * 32 + lane) * 2);
                bf[0] = v.x; bf[1] = v.y;
#pragma unroll
                for (int ii = 0; ii < 4; ii++)
                    mma_f16(acc[ii][jj], af[ii], bf);
            }
        }
    }

    // Epilogue: m16n8 f32 D frag: c0,c1 at (r=lane/4, col=2*(lane%4)+{0,1}); c2,c3 at r+8.
    const int hout = h0 + row;
#pragma unroll
    for (int ii = 0; ii < 4; ii++) {
        int o0 = my * 128 + wm * 64 + ii * 16 + (lane >> 2);
#pragma unroll
        for (int jj = 0; jj < 8; jj++) {
            int w0 = jj * 8 + (lane & 3) * 2;
            float* p = out + ((size_t)(b * COUT + o0) * H_ + hout) * W_ + w0;
            *(float2*)p = make_float2(acc[ii][jj][0], acc[ii][jj][1]);
            *(float2*)(p + 8 * H_ * W_) = make_float2(acc[ii][jj][2], acc[ii][jj][3]);
        }
    }
}

// ---------------------------------------------------------------------------
extern "C" void kernel_launch(void* const* d_in, const int* in_sizes, int n_in,
                              void* d_out, int out_size) {
    const float* x       = (const float*)d_in[0];   // [16,256,64,64]
    const float* thetas  = (const float*)d_in[1];   // [16,4]
    const float* scales  = (const float*)d_in[2];   // [16,4]
    const float* lambdas = (const float*)d_in[3];   // [16,4]
    const float* weight  = (const float*)d_in[4];   // [4,256,256,3,3]
    float* out = (float*)d_out;                     // [16,256,64,64]

    pad_kernel<<<B_ * 66, 256>>>(x);
    wtrans_kernel<<<dim3(256, 16), 256>>>(weight, thetas, scales, lambdas);

    cudaFuncSetAttribute(conv_mma_kernel,
                         cudaFuncAttributeMaxDynamicSharedMemorySize, DYN_SMEM);
    conv_mma_kernel<<<dim3(32, 2, 16), 128, DYN_SMEM>>>(out);
}

// round 16
// speedup vs baseline: 1.1361x; 1.1361x over previous
#include <cuda_runtime.h>
#include <cuda_fp16.h>
#include <math_constants.h>
#include <cstdint>

#define B_   16
#define CIN  256
#define COUT 256
#define H_   64
#define W_   64
#define NK   4

// ---------------------------------------------------------------------------
// Device scratch (allocation-free rule)
// ---------------------------------------------------------------------------
// A operand (fp16, m16n8k16 fragment order):
//   per (b,tap): [gk 16][mtile 16][lane 32][8 halves] = 65536 halves
__device__ __align__(1024) __half g_WtFh[(size_t)B_ * 9 * 65536];          // 18.9 MB
// B operand (fp16 fragment order), 3 dx-shifted padded copies:
//   per (dx,b,h): [gk 16][w8 8][lane 32][2 u32] = 16384 halves
__device__ __align__(1024) __half g_xBFh[(size_t)3 * B_ * 66 * 16384];     // 103.8 MB

// ---------------------------------------------------------------------------
__device__ __forceinline__ uint32_t smem_u32(const void* p) {
    uint32_t a;
    asm("{ .reg .u64 t; cvta.to.shared.u64 t, %1; cvt.u32.u64 %0, t; }" : "=r"(a) : "l"(p));
    return a;
}
#define CP_ASYNC16(sm, g) \
    asm volatile("cp.async.cg.shared.global [%0], [%1], 16;" :: "r"(sm), "l"(g))
#define CP_COMMIT() asm volatile("cp.async.commit_group;" ::: "memory")
#define CP_WAIT2()  asm volatile("cp.async.wait_group 2;" ::: "memory")

__device__ __forceinline__ void mma_f16(float* d, const uint32_t* a, const uint32_t* b) {
    asm volatile(
        "mma.sync.aligned.m16n8k16.row.col.f32.f16.f16.f32 "
        "{%0,%1,%2,%3}, {%4,%5,%6,%7}, {%8,%9}, {%0,%1,%2,%3};"
        : "+f"(d[0]), "+f"(d[1]), "+f"(d[2]), "+f"(d[3])
        : "r"(a[0]), "r"(a[1]), "r"(a[2]), "r"(a[3]), "r"(b[0]), "r"(b[1]));
}

// ---------------------------------------------------------------------------
// Build one 9x9 interpolation matrix (scaled by lambda) into R[81].
// ---------------------------------------------------------------------------
__device__ void rot_build(float t, float s, float lam, float* R) {
    float x = cosf(t) * s;
    float y = sinf(t) * s;

    float M[81];
#pragma unroll
    for (int i = 0; i < 81; i++) M[i] = 0.f;

    bool pos = (t >= 0.f);
    bool big = (s >= 1.f);
    bool m1  = (fabsf(t) <= (float)(CUDART_PI / 4.0));

    if (pos) {
        float a = x - y, b = x * y, c = x + y, d = a * c, e = a + c;
        if (m1 && big) {
            M[0] = a;        M[1] = 1.f - a;
            M[9+1] = 1.f-y;  M[9+2] = y;
            M[18+2] = a;     M[18+5] = 1.f-a;
            M[27+0] = y;     M[27+3] = 1.f-y;
            M[45+5] = 1.f-y; M[45+8] = y;
            M[54+3] = 1.f-a; M[54+6] = a;
            M[63+6] = y;     M[63+7] = 1.f-y;
            M[72+7] = 1.f-a; M[72+8] = a;
        } else if (m1 && !big) {
            M[0] = d;  M[1] = a-d;  M[3] = c-d;  M[4] = 1.f-e+d;
            M[9+1] = x-b;  M[9+2] = b;  M[9+4] = 1.f-c+b;  M[9+5] = y-b;
            M[18+1] = c-d; M[18+2] = d; M[18+4] = 1.f-e+d; M[18+5] = a-d;
            M[27+0] = b;   M[27+1] = y-b; M[27+3] = x-b;   M[27+4] = 1.f-c+b;
            M[45+4] = 1.f-c+b; M[45+5] = x-b; M[45+7] = y-b; M[45+8] = b;
            M[54+3] = a-d; M[54+4] = 1.f-e+d; M[54+6] = d;  M[54+7] = c-d;
            M[63+3] = y-b; M[63+4] = 1.f-c+b; M[63+6] = b;  M[63+7] = x-b;
            M[72+4] = 1.f-e+d; M[72+5] = c-d; M[72+7] = a-d; M[72+8] = d;
        } else {
            M[0] = a;        M[1] = 1.f-a;
            M[9+1] = x-b;    M[9+2] = b;   M[9+4] = 1.f-c+b; M[9+5] = y-b;
            M[18+2] = a;     M[18+5] = 1.f-a;
            M[27+0] = b;     M[27+1] = y-b; M[27+3] = x-b;  M[27+4] = 1.f-c+b;
            M[45+4] = 1.f-c+b; M[45+5] = x-b; M[45+7] = y-b; M[45+8] = b;
            M[54+3] = 1.f-a; M[54+6] = a;
            M[63+3] = y-b;   M[63+4] = 1.f-c+b; M[63+6] = b; M[63+7] = x-b;
            M[72+7] = 1.f-a; M[72+8] = a;
        }
    } else {
        float yp = -y;
        float ap = x - yp, bp = x * yp, cp = x + yp, dp = ap * cp, ep = ap + cp;
        if (m1 && big) {
            M[0] = cp;        M[3] = 1.f-cp;
            M[9+0] = yp;      M[9+1] = 1.f-yp;
            M[18+1] = 1.f-cp; M[18+2] = cp;
            M[27+3] = 1.f-yp; M[27+6] = yp;
            M[45+2] = yp;     M[45+5] = 1.f-yp;
            M[54+6] = cp;     M[54+7] = 1.f-cp;
            M[63+7] = 1.f-yp; M[63+8] = yp;
            M[72+5] = 1.f-cp; M[72+8] = cp;
        } else if (m1 && !big) {
            M[0] = dp;  M[1] = cp-dp;  M[3] = ap-dp;  M[4] = 1.f-ep+dp;
            M[9+0] = bp;   M[9+1] = x-bp;  M[9+3] = yp-bp;   M[9+4] = 1.f-cp+bp;
            M[18+1] = ap-dp; M[18+2] = dp; M[18+4] = 1.f-ep+dp; M[18+5] = cp-dp;
            M[27+1] = yp-bp; M[27+2] = bp; M[27+4] = 1.f-cp+bp; M[27+5] = x-bp;
            M[45+3] = x-bp;  M[45+4] = 1.f-cp+bp; M[45+6] = bp; M[45+7] = yp-bp;
            M[54+3] = cp-dp; M[54+4] = 1.f-ep+dp; M[54+6] = dp; M[54+7] = ap-dp;
            M[63+4] = 1.f-cp+bp; M[63+5] = yp-bp; M[63+7] = x-bp; M[63+8] = bp;
            M[72+4] = 1.f-ep+dp; M[72+5] = ap-dp; M[72+7] = cp-dp; M[72+8] = dp;
        } else {
            M[0] = cp;        M[3] = 1.f-cp;
            M[9+0] = bp;      M[9+1] = x-bp; M[9+3] = yp-bp; M[9+4] = 1.f-cp+bp;
            M[18+1] = 1.f-cp; M[18+2] = cp;
            M[27+3] = x-bp;   M[27+4] = 1.f-cp+bp; M[27+6] = bp; M[27+7] = yp-bp;
            M[45+1] = yp-bp;  M[45+2] = bp; M[45+4] = 1.f-cp+bp; M[45+5] = x-bp;
            M[54+6] = cp;     M[54+7] = 1.f-cp;
            M[63+4] = 1.f-cp+bp; M[63+5] = yp-bp; M[63+7] = x-bp; M[63+8] = bp;
            M[72+5] = 1.f-cp; M[72+8] = cp;
        }
    }
    M[40] = 1.f;

#pragma unroll
    for (int i = 0; i < 81; i++) R[i] = M[i] * lam;
}

// ---------------------------------------------------------------------------
// Kernel 1 (fused rot + wtrans): transformed weights -> A fp16 fragment order.
// Grid (256 o, 16 b), 256 threads = c. Threads 0..3 build the rot matrices.
// ---------------------------------------------------------------------------
__global__ void wtrans_kernel(const float* __restrict__ weight,
                              const float* __restrict__ thetas,
                              const float* __restrict__ scales,
                              const float* __restrict__ lambdas) {
    __shared__ float rs[NK * 81];
    int b = blockIdx.y;
    int o = blockIdx.x;
    int c = threadIdx.x;
    if (c < NK) {
        int idx = b * NK + c;
        rot_build(thetas[idx], scales[idx], lambdas[idx], &rs[c * 81]);
    }
    __syncthreads();

    float acc[9];
#pragma unroll
    for (int i = 0; i < 9; i++) acc[i] = 0.f;

#pragma unroll
    for (int n = 0; n < NK; n++) {
        const float* wp = weight + (((size_t)n * COUT + o) * CIN + c) * 9;
        float wv[9];
#pragma unroll
        for (int j = 0; j < 9; j++) wv[j] = wp[j];
        const float* r = &rs[n * 81];
#pragma unroll
        for (int i = 0; i < 9; i++)
#pragma unroll
            for (int j = 0; j < 9; j++)
                acc[i] = fmaf(r[i * 9 + j], wv[j], acc[i]);
    }

    int gk     = c >> 4;              // 16-channel group
    int mtile  = o >> 4;
    int lane   = (o & 7) * 4 + ((c >> 1) & 3);
    int r      = ((o >> 3) & 1) | (((c >> 3) & 1) << 1);
    int t      = c & 1;
    size_t base = (size_t)(b * 9) * 65536
                + ((size_t)gk * 16 + mtile) * 256 + lane * 8 + r * 2 + t;
#pragma unroll
    for (int tap = 0; tap < 9; tap++)
        g_WtFh[base + (size_t)tap * 65536] = __float2half(acc[tap]);
}

// ---------------------------------------------------------------------------
// Kernel 2: x -> B fp16 fragment order, 3 dx copies from ONE smem staging pass.
// Block = (b,h): 1056 blocks, 256 threads.
// smem transposed [w][c], row stride 258 halves (516B: bank step 1/w,
// conflict-free). Fragment assembly via 4x LDS.32 (4B-aligned always) +
// 1x STG.128 per 16 output bytes.
// ---------------------------------------------------------------------------
__global__ void pad_kernel(const float* __restrict__ x) {
    __shared__ __half sxt[64 * 258];      // [w][c], row stride 258 halves
    int id = blockIdx.x;                  // b*66 + h
    int h = id % 66;
    int b = id / 66;
    int hs = h - 1;
    bool hok = (hs >= 0 && hs < H_);
    int tid = threadIdx.x;

    if (hok) {
        int wl = tid & 63;
        int cs = tid >> 6;
        for (int c0 = 0; c0 < 256; c0 += 4) {
            int c = c0 + cs;
            float v = x[((size_t)(b * CIN + c) * H_ + hs) * W_ + wl];
            sxt[wl * 258 + c] = __float2half(v);
        }
    }
    __syncthreads();

    // per-thread v decode (shared across the 3 dx copies):
    // uint4 v covers lanes 2(v&15), 2(v&15)+1, regs 0..1 of (gk, w8)
    for (int dx = 0; dx < 3; dx++) {
        uint4* dst = (uint4*)(g_xBFh + ((size_t)(dx * 16 + b) * 66 + h) * 16384);
#pragma unroll
        for (int r = 0; r < 8; r++) {
            int v  = tid + r * 256;           // 0..2047
            int gk = v >> 7;
            int w8 = (v >> 4) & 7;
            int a  = (2 * v) & 3;             // 0 or 2 (lane&3 of first lane)
            int wl = ((2 * v) & 31) >> 2;
            int w  = w8 * 8 + wl - 1 + dx;
            uint4 outv = make_uint4(0u, 0u, 0u, 0u);
            if (hok && w >= 0 && w < W_) {
                // halves base gk*16 within row w (even half offset -> 4B aligned)
                const uint32_t* rowp = (const uint32_t*)&sxt[w * 258 + gk * 16];
                // u32 index i = halves (2i, 2i+1)
                outv.x = rowp[a];             // c(2a), c(2a)+1
                outv.y = rowp[a + 4];         // +8 channels (reg 1)
                outv.z = rowp[a + 1];         // lane+1, reg 0
                outv.w = rowp[a + 5];         // lane+1, reg 1
            }
            dst[v] = outv;
        }
    }
}

// ---------------------------------------------------------------------------
// Kernel 3: fp16 mma.sync (m16n8k16) GEMM conv.  (R12 configuration)
// CTA: 128 o x 128 n (2 rows x 64 w), 128 threads, 4 warps (2m x 2n),
// warp tile 64 x 64. K = 72 chunks of 32 c (tap-major; 2 k16 steps each).
// 4-stage cp.async pipeline, 16KB/stage -> 64KB smem, 2 CTAs/SM.
// ---------------------------------------------------------------------------
#define STAGE_U32 4096                  // uint32 per stage (16KB)
#define DYN_SMEM (4 * STAGE_U32 * 4)

__global__ void __launch_bounds__(128, 2)
conv_mma_kernel(float* __restrict__ out) {
    extern __shared__ uint32_t sm[];

    const int tid = threadIdx.x;
    const int wid = tid >> 5;
    const int lane = tid & 31;
    const int b  = blockIdx.z;
    const int my = blockIdx.y;          // m tile (0..1)
    const int h0 = blockIdx.x * 2;      // output rows h0..h0+1

    const int wm = wid >> 1;            // 0..1  (warp m: 64 rows)
    const int row = wid & 1;            // warp n: one full output row (64 w)

    const uint32_t smb = smem_u32(sm);

    float acc[4][8][4];
#pragma unroll
    for (int i = 0; i < 4; i++)
#pragma unroll
        for (int j = 0; j < 8; j++)
#pragma unroll
            for (int k = 0; k < 4; k++) acc[i][j][k] = 0.f;

    const __half* Abase = g_WtFh + (size_t)b * 9 * 65536;
    const __half* Bbase = g_xBFh;

    auto issue_stage = [&](int chunk, int slot) {
        int tap = chunk >> 3;
        int q   = chunk & 7;                          // cchunk (32 c)
        int dy  = tap / 3, dx = tap - dy * 3;
        uint32_t sbase = smb + slot * (STAGE_U32 * 4);
        const __half* Ab = Abase + (size_t)tap * 65536;
        size_t bhbase = ((size_t)(dx * 16 + b) * 66 + (h0 + dy)) * 16384;
        // A: 512 x 16B
#pragma unroll
        for (int r = 0; r < 4; r++) {
            int u = tid + r * 128;                    // 0..511
            int kstep = u >> 8;
            int mtl   = (u >> 5) & 7;
            int ln    = u & 31;
            const __half* g = Ab + ((size_t)(q * 2 + kstep) * 16 + (my * 8 + mtl)) * 256 + ln * 8;
            CP_ASYNC16(sbase + u * 16, g);
        }
        // B: 512 x 16B (two h rows)
#pragma unroll
        for (int r = 0; r < 4; r++) {
            int u = tid + r * 128;                    // 0..511
            int kstep = u >> 8;
            int rw    = (u >> 7) & 1;
            int w8    = (u >> 4) & 7;
            int lp    = u & 15;
            const __half* g = Bbase + bhbase + (size_t)rw * 16384
                              + ((size_t)(q * 2 + kstep) * 8 + w8) * 128 + lp * 8;
            CP_ASYNC16(sbase + 8192 + u * 16, g);
        }
    };

    issue_stage(0, 0); CP_COMMIT();
    issue_stage(1, 1); CP_COMMIT();
    issue_stage(2, 2); CP_COMMIT();

    for (int i = 0; i < 72; i++) {
        CP_WAIT2();
        __syncthreads();
        if (i + 3 < 72) issue_stage(i + 3, (i + 3) & 3);
        CP_COMMIT();

        const uint32_t* st = sm + (i & 3) * STAGE_U32;
#pragma unroll
        for (int kstep = 0; kstep < 2; kstep++) {
            uint32_t af[4][4];
#pragma unroll
            for (int ii = 0; ii < 4; ii++) {
                const uint4 v = *(const uint4*)(st + ((kstep * 8 + wm * 4 + ii) * 32 + lane) * 4);
                af[ii][0] = v.x; af[ii][1] = v.y; af[ii][2] = v.z; af[ii][3] = v.w;
            }
#pragma unroll
            for (int jj = 0; jj < 8; jj++) {
                uint32_t bf[2];
                const uint2 v = *(const uint2*)(st + 2048 +
                                 (((kstep * 2 + row) * 8 + jj) * 32 + lane) * 2);
                bf[0] = v.x; bf[1] = v.y;
#pragma unroll
                for (int ii = 0; ii < 4; ii++)
                    mma_f16(acc[ii][jj], af[ii], bf);
            }
        }
    }

    // Epilogue: m16n8 f32 D frag: c0,c1 at (r=lane/4, col=2*(lane%4)+{0,1}); c2,c3 at r+8.
    const int hout = h0 + row;
#pragma unroll
    for (int ii = 0; ii < 4; ii++) {
        int o0 = my * 128 + wm * 64 + ii * 16 + (lane >> 2);
#pragma unroll
        for (int jj = 0; jj < 8; jj++) {
            int w0 = jj * 8 + (lane & 3) * 2;
            float* p = out + ((size_t)(b * COUT + o0) * H_ + hout) * W_ + w0;
            *(float2*)p = make_float2(acc[ii][jj][0], acc[ii][jj][1]);
            *(float2*)(p + 8 * H_ * W_) = make_float2(acc[ii][jj][2], acc[ii][jj][3]);
        }
    }
}

// ---------------------------------------------------------------------------
extern "C" void kernel_launch(void* const* d_in, const int* in_sizes, int n_in,
                              void* d_out, int out_size) {
    const float* x       = (const float*)d_in[0];   // [16,256,64,64]
    const float* thetas  = (const float*)d_in[1];   // [16,4]
    const float* scales  = (const float*)d_in[2];   // [16,4]
    const float* lambdas = (const float*)d_in[3];   // [16,4]
    const float* weight  = (const float*)d_in[4];   // [4,256,256,3,3]
    float* out = (float*)d_out;                     // [16,256,64,64]

    pad_kernel<<<B_ * 66, 256>>>(x);
    wtrans_kernel<<<dim3(256, 16), 256>>>(weight, thetas, scales, lambdas);

    cudaFuncSetAttribute(conv_mma_kernel,
                         cudaFuncAttributeMaxDynamicSharedMemorySize, DYN_SMEM);
    conv_mma_kernel<<<dim3(32, 2, 16), 128, DYN_SMEM>>>(out);
}